// round 10
// baseline (speedup 1.0000x reference)
#include <cuda_runtime.h>
#include <cuda_bf16.h>
#include <math.h>
#include <stdint.h>

#define B   2
#define H   16
#define L   2048
#define DH  64
#define DM  1024
#define PE  (B * H * L * DH)     // 4,194,304 == B*L*DM
#define WE  (DM * DM)

typedef unsigned short u16;
typedef unsigned int   u32;

// ---------------- device scratch (allocation-free, 16B-aligned) ----------------
__device__ __align__(16) u16 g_xh[3][PE], g_xl[3][PE];     // q,k,v inputs split
__device__ __align__(16) u16 g_wh[3][WE], g_wl[3][WE];     // Wq,Wk,Wv split
__device__ __align__(16) u16 g_qhh[PE], g_qhl[PE];         // projected head-major [bh][l][64]
__device__ __align__(16) u16 g_khh[PE], g_khl[PE];
__device__ __align__(16) u16 g_vhh[PE], g_vhl[PE];
__device__ __align__(16) u32 g_mskb[(size_t)B * L * (L / 32)];  // bit-packed mask [row][64]
__device__ unsigned char g_rowE[B * L];

// ---------------- helpers ----------------
__device__ __forceinline__ void mma_bf16(float* c, u32 a0, u32 a1, u32 a2, u32 a3,
                                         u32 b0, u32 b1) {
    asm volatile(
        "mma.sync.aligned.m16n8k16.row.col.f32.bf16.bf16.f32 "
        "{%0,%1,%2,%3},{%4,%5,%6,%7},{%8,%9},{%0,%1,%2,%3};"
        : "+f"(c[0]), "+f"(c[1]), "+f"(c[2]), "+f"(c[3])
        : "r"(a0), "r"(a1), "r"(a2), "r"(a3), "r"(b0), "r"(b1));
}

__device__ __forceinline__ void ldsm4(u32& r0, u32& r1, u32& r2, u32& r3, u32 a) {
    asm volatile("ldmatrix.sync.aligned.m8n8.x4.shared.b16 {%0,%1,%2,%3}, [%4];"
                 : "=r"(r0), "=r"(r1), "=r"(r2), "=r"(r3) : "r"(a));
}
__device__ __forceinline__ void ldsm4t(u32& r0, u32& r1, u32& r2, u32& r3, u32 a) {
    asm volatile("ldmatrix.sync.aligned.m8n8.x4.trans.shared.b16 {%0,%1,%2,%3}, [%4];"
                 : "=r"(r0), "=r"(r1), "=r"(r2), "=r"(r3) : "r"(a));
}

__device__ __forceinline__ u32 pk2(float lo, float hi) {
    u32 r;
    asm("cvt.rn.bf16x2.f32 %0, %1, %2;" : "=r"(r) : "f"(hi), "f"(lo));
    return r;
}

__device__ __forceinline__ u32 pklo(float v0, float v1, __nv_bfloat16 h0, __nv_bfloat16 h1) {
    float l0 = v0 - __bfloat162float(h0);
    float l1 = v1 - __bfloat162float(h1);
    return pk2(l0, l1);
}

// FFMA-only exp (MUFU would bottleneck 134M exps). Inputs bounded |x| small.
__device__ __forceinline__ float fast_exp(float x) {
    float y = x * 1.44269504088896f;
    float t = __fadd_rn(y, 12582912.0f);
    float r = __fsub_rn(t, 12582912.0f);
    float f = __fsub_rn(y, r);
    float p = 1.33335581e-3f;
    p = fmaf(p, f, 9.61812910e-3f);
    p = fmaf(p, f, 5.55041087e-2f);
    p = fmaf(p, f, 2.40226507e-1f);
    p = fmaf(p, f, 6.93147181e-1f);
    p = fmaf(p, f, 1.0f);
    int sc = (__float_as_int(t) << 23) + 0x3f800000;
    return p * __int_as_float(sc);
}

__device__ __forceinline__ u32 s2u(const void* p) {
    return (u32)__cvta_generic_to_shared(p);
}
__device__ __forceinline__ void cpa16(u32 saddr, const void* g) {
    asm volatile("cp.async.cg.shared.global [%0], [%1], 16;" :: "r"(saddr), "l"(g));
}
__device__ __forceinline__ void cpa8(u32 saddr, const void* g) {
    asm volatile("cp.async.ca.shared.global [%0], [%1], 8;" :: "r"(saddr), "l"(g));
}
#define CP_COMMIT() asm volatile("cp.async.commit_group;" ::: "memory")
#define CP_WAIT(n)  asm volatile("cp.async.wait_group %0;" :: "n"(n) : "memory")

// ---------------- prep: fp32 -> bf16 hi/lo split (3 tensors per launch) ----------------
__global__ __launch_bounds__(256) void conv3(const float* __restrict__ p0,
                                             const float* __restrict__ p1,
                                             const float* __restrict__ p2,
                                             int base, int n4) {
    int i = blockIdx.x * 256 + threadIdx.x;
    if (i >= n4) return;
    int z = blockIdx.z;
    const float* in = (z == 0) ? p0 : (z == 1) ? p1 : p2;
    int slot = base + z;
    u16* hi = (slot < 3) ? g_xh[slot] : g_wh[slot - 3];
    u16* lo = (slot < 3) ? g_xl[slot] : g_wl[slot - 3];
    float4 v = ((const float4*)in)[i];
    __nv_bfloat16 h0 = __float2bfloat16(v.x), h1 = __float2bfloat16(v.y);
    __nv_bfloat16 h2 = __float2bfloat16(v.z), h3 = __float2bfloat16(v.w);
    u32 hp0 = (u32)__bfloat16_as_ushort(h0) | ((u32)__bfloat16_as_ushort(h1) << 16);
    u32 hp1 = (u32)__bfloat16_as_ushort(h2) | ((u32)__bfloat16_as_ushort(h3) << 16);
    ((uint2*)hi)[i] = make_uint2(hp0, hp1);
    ((uint2*)lo)[i] = make_uint2(pklo(v.x, v.y, h0, h1), pklo(v.z, v.w, h2, h3));
}

// ---------------- prep: mask -> packed bits + row-empty flags ----------------
__global__ __launch_bounds__(256) void maskprep(const int* __restrict__ mask) {
    int row  = blockIdx.x * 8 + (threadIdx.x >> 5);
    int lane = threadIdx.x & 31;
    const int* src = mask + (size_t)row * L;
    int cnt = 0;
#pragma unroll
    for (int half = 0; half < 2; half++) {
        int c0 = (lane + half * 32) * 32;
        u32 wbits = 0;
#pragma unroll
        for (int j = 0; j < 32; j += 4) {
            int4 m = *(const int4*)&src[c0 + j];
            wbits |= ((u32)(m.x != 0) << j) | ((u32)(m.y != 0) << (j + 1)) |
                     ((u32)(m.z != 0) << (j + 2)) | ((u32)(m.w != 0) << (j + 3));
        }
        g_mskb[(size_t)row * 64 + lane + half * 32] = wbits;
        cnt += __popc(wbits);
    }
#pragma unroll
    for (int o = 16; o > 0; o >>= 1) cnt += __shfl_xor_sync(0xffffffffu, cnt, o);
    if (lane == 0) g_rowE[row] = (cnt == 0) ? 1 : 0;
}

// ---------------- projection GEMM (all 3 in one launch, cp.async + ldmatrix) ----------------
#define PJ_ARR (128 * 40)
#define PJ_STG (4 * PJ_ARR)

__global__ __launch_bounds__(256, 2) void proj_hmma(const float* __restrict__ b0p,
                                                    const float* __restrict__ b1p,
                                                    const float* __restrict__ b2p) {
    extern __shared__ __align__(16) u16 ps[];
    const int which = blockIdx.z;
    const float* bias = (which == 0) ? b0p : (which == 1) ? b1p : b2p;
    const float scale = (which == 0) ? 0.125f : 1.0f;

    const int tid = threadIdx.x, lane = tid & 31, warp = tid >> 5;
    const int wm = warp >> 1, wn = warp & 1, r = lane >> 2, qc = lane & 3;
    const int m0 = blockIdx.y * 128, n0 = blockIdx.x * 128;

    const u16 *Xh = g_xh[which], *Xl = g_xl[which];
    const u16 *Wh = g_wh[which], *Wl = g_wl[which];
    u16* oh = (which == 0) ? g_qhh : (which == 1) ? g_khh : g_vhh;
    u16* ol = (which == 0) ? g_qhl : (which == 1) ? g_khl : g_vhl;

    const int rowoff = ((lane >> 3) & 1) * 8 + (lane & 7);
    const int coloff = (lane >> 4) * 8;
    const u32 lobP = (u32)(rowoff * 40 + coloff) * 2;
    const u32 ps0 = s2u(ps);

    auto load_stage = [&](int kt, int st) {
        u16* sXh = ps + st * PJ_STG;
        u16* sXl = sXh + PJ_ARR;
        u16* sWh = sXl + PJ_ARR;
        u16* sWl = sWh + PJ_ARR;
        int k0 = kt * 32;
#pragma unroll
        for (int rr = 0; rr < 2; rr++) {
            int idx = tid + rr * 256;
            int row = idx >> 2, ch = idx & 3;
            int so = row * 40 + ch * 8;
            size_t gx = (size_t)(m0 + row) * DM + k0 + ch * 8;
            size_t gw = (size_t)(n0 + row) * DM + k0 + ch * 8;
            cpa16(s2u(sXh + so), Xh + gx);
            cpa16(s2u(sXl + so), Xl + gx);
            cpa16(s2u(sWh + so), Wh + gw);
            cpa16(s2u(sWl + so), Wl + gw);
        }
    };

    float acc[2][8][4] = {};

    load_stage(0, 0);
    CP_COMMIT();

    for (int kt = 0; kt < 32; kt++) {
        if (kt < 31) { load_stage(kt + 1, (kt + 1) & 1); CP_COMMIT(); CP_WAIT(1); }
        else         { CP_WAIT(0); }
        __syncthreads();

        const u32 stb = ps0 + (u32)((kt & 1) * PJ_STG) * 2;
        const u32 xa_h = stb + (u32)(wm * 32 * 40) * 2 + lobP;
        const u32 xa_l = xa_h + (u32)PJ_ARR * 2;
        const u32 wb_h = stb + (u32)(2 * PJ_ARR) * 2 + (u32)(wn * 64 * 40) * 2 + lobP;
        const u32 wb_l = wb_h + (u32)PJ_ARR * 2;

#pragma unroll
        for (int ks = 0; ks < 2; ks++) {
            u32 xh[2][4], xl[2][4];
#pragma unroll
            for (int mt = 0; mt < 2; mt++) {
                ldsm4(xh[mt][0], xh[mt][1], xh[mt][2], xh[mt][3], xa_h + mt * 1280 + ks * 32);
                ldsm4(xl[mt][0], xl[mt][1], xl[mt][2], xl[mt][3], xa_l + mt * 1280 + ks * 32);
            }
#pragma unroll
            for (int p = 0; p < 4; p++) {
                u32 t0, t1, t2, t3, u0, u1, u2, u3;
                ldsm4(t0, t1, t2, t3, wb_h + p * 1280 + ks * 32);
                ldsm4(u0, u1, u2, u3, wb_l + p * 1280 + ks * 32);
#pragma unroll
                for (int mt = 0; mt < 2; mt++) {
                    mma_bf16(acc[mt][2 * p],     xh[mt][0], xh[mt][1], xh[mt][2], xh[mt][3], t0, t2);
                    mma_bf16(acc[mt][2 * p],     xh[mt][0], xh[mt][1], xh[mt][2], xh[mt][3], u0, u2);
                    mma_bf16(acc[mt][2 * p],     xl[mt][0], xl[mt][1], xl[mt][2], xl[mt][3], t0, t2);
                    mma_bf16(acc[mt][2 * p + 1], xh[mt][0], xh[mt][1], xh[mt][2], xh[mt][3], t1, t3);
                    mma_bf16(acc[mt][2 * p + 1], xh[mt][0], xh[mt][1], xh[mt][2], xh[mt][3], u1, u3);
                    mma_bf16(acc[mt][2 * p + 1], xl[mt][0], xl[mt][1], xl[mt][2], xl[mt][3], t1, t3);
                }
            }
        }
        __syncthreads();
    }

    // epilogue: bias + scale, split hi/lo, head-major store
#pragma unroll
    for (int mt = 0; mt < 2; mt++)
#pragma unroll
        for (int nt = 0; nt < 8; nt++) {
            int j = n0 + wn * 64 + nt * 8 + qc * 2;
            int hh = j >> 6, d = j & 63;
            float b0f = bias[j], b1f = bias[j + 1];
#pragma unroll
            for (int half = 0; half < 2; half++) {
                int tok = m0 + wm * 32 + mt * 16 + r + half * 8;
                int bb = tok >> 11, l = tok & (L - 1);
                float v0 = (acc[mt][nt][half * 2 + 0] + b0f) * scale;
                float v1 = (acc[mt][nt][half * 2 + 1] + b1f) * scale;
                __nv_bfloat16 h0 = __float2bfloat16(v0), h1 = __float2bfloat16(v1);
                size_t o = ((size_t)(bb * H + hh) * L + l) * DH + d;
                *(u32*)&oh[o] = (u32)__bfloat16_as_ushort(h0) |
                                ((u32)__bfloat16_as_ushort(h1) << 16);
                *(u32*)&ol[o] = pklo(v0, v1, h0, h1);
            }
        }
}

// ---------------- fused attention (ldmatrix + cp.async, 2 CTAs/SM) ----------------
// Block = (b, h, 128 q-rows). 8 warps, warp owns 16 q-rows x full kv/d width.
// P hi/lo split; transposed B-fragments from ldmatrix.trans; mask bit-packed.
struct SAbuf {
    u16 Kh[64][72], Kl[64][72], Vh[64][72], Vl[64][72];
    u32 mkb[128][2];
};
struct SA {
    u16 Qh[128][72], Ql[128][72];
    SAbuf buf[2];
};

__global__ __launch_bounds__(256, 2) void attn_hmma(float* __restrict__ kout,
                                                    float* __restrict__ vout) {
    extern __shared__ __align__(16) char sraw[];
    SA* sm = (SA*)sraw;
    const int tid = threadIdx.x, lane = tid & 31, w = tid >> 5;
    const int r = lane >> 2, qc = lane & 3;
    const int h = blockIdx.x, qt = blockIdx.y, b = blockIdx.z;
    const int q0 = qt * 128, bh = b * H + h;

    const int rowoff = ((lane >> 3) & 1) * 8 + (lane & 7);
    const int coloff = (lane >> 4) * 8;
    const u32 lob = (u32)(rowoff * 72 + coloff) * 2;     // pitch 72 u16 = 144 B

    auto load_tile = [&](int kt, int bufi) {
        SAbuf& bf = sm->buf[bufi];
        const int k0 = kt * 64;
#pragma unroll
        for (int rr = 0; rr < 2; rr++) {
            int idx = tid + rr * 256;
            int ki = idx >> 3, ch = idx & 7;
            size_t gkv = ((size_t)bh * L + k0 + ki) * 64 + ch * 8;
            cpa16(s2u(&bf.Kh[ki][ch * 8]), g_khh + gkv);
            cpa16(s2u(&bf.Kl[ki][ch * 8]), g_khl + gkv);
            cpa16(s2u(&bf.Vh[ki][ch * 8]), g_vhh + gkv);
            cpa16(s2u(&bf.Vl[ki][ch * 8]), g_vhl + gkv);
        }
        if (tid < 128)
            cpa8(s2u(&bf.mkb[tid][0]),
                 g_mskb + ((size_t)(b * L + q0 + tid)) * 64 + (k0 >> 5));
    };

    // load Q tile (hi/lo) once, plain loads
    const u16* Qhg = g_qhh + ((size_t)bh * L + q0) * DH;
    const u16* Qlg = g_qhl + ((size_t)bh * L + q0) * DH;
#pragma unroll
    for (int rr = 0; rr < 4; rr++) {
        int idx = tid + rr * 256, qi = idx >> 3, ch = idx & 7;
        *(int4*)&sm->Qh[qi][ch * 8] = *(const int4*)&Qhg[qi * 64 + ch * 8];
        *(int4*)&sm->Ql[qi][ch * 8] = *(const int4*)&Qlg[qi * 64 + ch * 8];
    }
    const float rE0f = g_rowE[b * L + q0 + w * 16 + r] ? 1.0f : 0.0f;
    const float rE1f = g_rowE[b * L + q0 + w * 16 + r + 8] ? 1.0f : 0.0f;

    const u32 qa_h = s2u(&sm->Qh[w * 16][0]) + lob;
    const u32 qa_l = s2u(&sm->Ql[w * 16][0]) + lob;

    float av[8][4] = {}, ak[8][4] = {};
    float ls0 = 0.0f, ls1 = 0.0f;

    load_tile(0, 0);
    CP_COMMIT();

    for (int kt = 0; kt < L / 64; kt++) {
        if (kt < L / 64 - 1) { load_tile(kt + 1, (kt + 1) & 1); CP_COMMIT(); CP_WAIT(1); }
        else                 { CP_WAIT(0); }
        __syncthreads();
        SAbuf& bf = sm->buf[kt & 1];
        const u32 kb_h = s2u(bf.Kh) + lob;
        const u32 kb_l = s2u(bf.Kl) + lob;
        const u32 vb_h = s2u(bf.Vh) + lob;
        const u32 vb_l = s2u(bf.Vl) + lob;

        // ---- S = Qh*Kh + Ql*Kh + Qh*Kl ----
        float s[8][4] = {};
#pragma unroll
        for (int ks = 0; ks < 4; ks++) {
            u32 a0, a1, a2, a3, e0, e1, e2, e3;
            ldsm4(a0, a1, a2, a3, qa_h + ks * 32);
            ldsm4(e0, e1, e2, e3, qa_l + ks * 32);
#pragma unroll
            for (int p = 0; p < 4; p++) {
                u32 t0, t1, t2, t3, u0, u1, u2, u3;
                ldsm4(t0, t1, t2, t3, kb_h + p * 2304 + ks * 32);
                ldsm4(u0, u1, u2, u3, kb_l + p * 2304 + ks * 32);
                mma_bf16(s[2 * p],     a0, a1, a2, a3, t0, t2);
                mma_bf16(s[2 * p],     e0, e1, e2, e3, t0, t2);
                mma_bf16(s[2 * p],     a0, a1, a2, a3, u0, u2);
                mma_bf16(s[2 * p + 1], a0, a1, a2, a3, t1, t3);
                mma_bf16(s[2 * p + 1], e0, e1, e2, e3, t1, t3);
                mma_bf16(s[2 * p + 1], a0, a1, a2, a3, u1, u3);
            }
        }

        // ---- exp + bit-mask + rowsum + pack P hi/lo (in regs) ----
        uint2 mwa = *(const uint2*)&bf.mkb[w * 16 + r][0];
        uint2 mwb = *(const uint2*)&bf.mkb[w * 16 + r + 8][0];
        u32 pb[8][2], pl[8][2];
#pragma unroll
        for (int nt = 0; nt < 8; nt++) {
            int c0 = nt * 8 + qc * 2;
            u32 w0 = (c0 & 32) ? mwa.y : mwa.x;
            u32 w1 = (c0 & 32) ? mwb.y : mwb.x;
            int bit = c0 & 31;
            float m00 = (float)((w0 >> bit) & 1), m01 = (float)((w0 >> (bit + 1)) & 1);
            float m10 = (float)((w1 >> bit) & 1), m11 = (float)((w1 >> (bit + 1)) & 1);
            float p00 = fmaf(fast_exp(s[nt][0]), m00, rE0f);
            float p01 = fmaf(fast_exp(s[nt][1]), m01, rE0f);
            float p10 = fmaf(fast_exp(s[nt][2]), m10, rE1f);
            float p11 = fmaf(fast_exp(s[nt][3]), m11, rE1f);
            ls0 += p00 + p01;
            ls1 += p10 + p11;
            __nv_bfloat16 h00 = __float2bfloat16(p00), h01 = __float2bfloat16(p01);
            __nv_bfloat16 h10 = __float2bfloat16(p10), h11 = __float2bfloat16(p11);
            pb[nt][0] = (u32)__bfloat16_as_ushort(h00) | ((u32)__bfloat16_as_ushort(h01) << 16);
            pb[nt][1] = (u32)__bfloat16_as_ushort(h10) | ((u32)__bfloat16_as_ushort(h11) << 16);
            pl[nt][0] = pklo(p00, p01, h00, h01);
            pl[nt][1] = pklo(p10, p11, h10, h11);
        }

        // ---- P@V and P@K via ldmatrix.trans on row-major V/K tiles ----
#pragma unroll
        for (int kc = 0; kc < 4; kc++) {
            u32 a0 = pb[2 * kc][0], a1 = pb[2 * kc][1];
            u32 a2 = pb[2 * kc + 1][0], a3 = pb[2 * kc + 1][1];
            u32 c0 = pl[2 * kc][0], c1 = pl[2 * kc][1];
            u32 c2 = pl[2 * kc + 1][0], c3 = pl[2 * kc + 1][1];
#pragma unroll
            for (int p = 0; p < 4; p++) {
                u32 t0, t1, t2, t3;
                ldsm4t(t0, t1, t2, t3, vb_h + kc * 2304 + p * 32);
                mma_bf16(av[2 * p],     a0, a1, a2, a3, t0, t1);
                mma_bf16(av[2 * p],     c0, c1, c2, c3, t0, t1);
                mma_bf16(av[2 * p + 1], a0, a1, a2, a3, t2, t3);
                mma_bf16(av[2 * p + 1], c0, c1, c2, c3, t2, t3);
                ldsm4t(t0, t1, t2, t3, vb_l + kc * 2304 + p * 32);
                mma_bf16(av[2 * p],     a0, a1, a2, a3, t0, t1);
                mma_bf16(av[2 * p + 1], a0, a1, a2, a3, t2, t3);
                ldsm4t(t0, t1, t2, t3, kb_h + kc * 2304 + p * 32);
                mma_bf16(ak[2 * p],     a0, a1, a2, a3, t0, t1);
                mma_bf16(ak[2 * p],     c0, c1, c2, c3, t0, t1);
                mma_bf16(ak[2 * p + 1], a0, a1, a2, a3, t2, t3);
                mma_bf16(ak[2 * p + 1], c0, c1, c2, c3, t2, t3);
                ldsm4t(t0, t1, t2, t3, kb_l + kc * 2304 + p * 32);
                mma_bf16(ak[2 * p],     a0, a1, a2, a3, t0, t1);
                mma_bf16(ak[2 * p + 1], a0, a1, a2, a3, t2, t3);
            }
        }
        __syncthreads();
    }

    // ---- epilogue: normalize, store ----
    ls0 += __shfl_xor_sync(0xffffffffu, ls0, 1);
    ls0 += __shfl_xor_sync(0xffffffffu, ls0, 2);
    ls1 += __shfl_xor_sync(0xffffffffu, ls1, 1);
    ls1 += __shfl_xor_sync(0xffffffffu, ls1, 2);
    float inv0 = 1.0f / ls0, inv1 = 1.0f / ls1;
    int qr = q0 + w * 16 + r;
#pragma unroll
    for (int dt = 0; dt < 8; dt++) {
        int d = h * 64 + dt * 8 + qc * 2;
        size_t o0 = ((size_t)(b * L + qr)) * DM + d;
        size_t o1 = ((size_t)(b * L + qr + 8)) * DM + d;
        float2 t;
        t.x = ak[dt][0] * inv0; t.y = ak[dt][1] * inv0; *(float2*)&kout[o0] = t;
        t.x = ak[dt][2] * inv1; t.y = ak[dt][3] * inv1; *(float2*)&kout[o1] = t;
        t.x = av[dt][0] * inv0; t.y = av[dt][1] * inv0; *(float2*)&vout[o0] = t;
        t.x = av[dt][2] * inv1; t.y = av[dt][3] * inv1; *(float2*)&vout[o1] = t;
    }
}

// ---------------- launch ----------------
extern "C" void kernel_launch(void* const* d_in, const int* in_sizes, int n_in,
                              void* d_out, int out_size)
{
    const float* qkv[3] = {nullptr, nullptr, nullptr}; int nq = 0;
    const float* Ws[3]  = {nullptr, nullptr, nullptr}; int nw = 0;
    const float* bs[3]  = {nullptr, nullptr, nullptr}; int nb = 0;
    const int* mask = nullptr;
    for (int i = 0; i < n_in; i++) {
        int sz = in_sizes[i];
        if (sz == B * L * DM)      { if (nq < 3) qkv[nq++] = (const float*)d_in[i]; }
        else if (sz == B * L * L)  { mask = (const int*)d_in[i]; }
        else if (sz == DM * DM)    { if (nw < 3) Ws[nw++] = (const float*)d_in[i]; }
        else if (sz == DM)         { if (nb < 3) bs[nb++] = (const float*)d_in[i]; }
    }
    if (!mask || nq < 3 || nw < 3 || nb < 3) return;

    float* kout = (float*)d_out;
    float* vout = kout + (size_t)B * L * DM;

    conv3<<<dim3(PE / 4 / 256, 1, 3), 256>>>(qkv[0], qkv[1], qkv[2], 0, PE / 4);
    conv3<<<dim3(WE / 4 / 256, 1, 3), 256>>>(Ws[0], Ws[1], Ws[2], 3, WE / 4);
    maskprep<<<(B * L) / 8, 256>>>(mask);

    int psm = 2 * PJ_STG * (int)sizeof(u16);   // 81920
    cudaFuncSetAttribute(proj_hmma, cudaFuncAttributeMaxDynamicSharedMemorySize, psm);
    proj_hmma<<<dim3(DM / 128, (B * L) / 128, 3), 256, psm>>>(bs[0], bs[1], bs[2]);

    int asm_ = (int)sizeof(SA);                // 112640
    cudaFuncSetAttribute(attn_hmma, cudaFuncAttributeMaxDynamicSharedMemorySize, asm_);
    attn_hmma<<<dim3(H, L / 128, B), 256, asm_>>>(kout, vout);
}